// round 12
// baseline (speedup 1.0000x reference)
#include <cuda_runtime.h>
#include <math.h>
#include <stdint.h>

#define D       256
#define K       8
#define FULLM   0xffffffffu

typedef unsigned long long u64;

// ---- k_assign (MMA, A/B-phase) config ----
#define A_TPB    64
#define A_WPB    2
#define A_GRID   444                  // 3 CTAs/SM * 148
#define A_WARPS  (A_GRID * A_WPB)     // 888
#define AP       68                   // quarter pitch (floats)
#define SLOTF    (16 * AP)            // floats per slot
#define SLOTB    (SLOTF * 4)          // 4352 B per slot
// dynamic smem offsets (bytes)
#define OFF_P    0                    // protos [q][k][AP] = 8704 B
#define OFF_TILE 8704                 // 2 warps * 4 slots * 4352 = 34816 B
#define OFF_ACC  43520                // 2 warps * 8192 = 16384 B
#define OFF_ICNT 59904                // 16 ints
#define A_SMEM   59968

// ---- k_loss (MMA) config — R9 verbatim ----
#define L_TPB   64
#define L_CTAS  740                   // 5 * 148
#define L_TOTW  (L_CTAS * 2)
#define PITCH   260

// ---- device scratch ----
__device__ float g_part_sums[A_GRID * K * D];
__device__ int   g_part_counts[A_GRID * K];
__device__ float g_mid[8 * K * D];
__device__ float g_part_loss[L_CTAS];
__device__ float g_protos_new[K * D];

// ---------------- helpers ----------------
__device__ __forceinline__ u64 pk2(float lo, float hi) {
    u64 r; asm("mov.b64 %0, {%1, %2};" : "=l"(r) : "f"(lo), "f"(hi)); return r;
}
__device__ __forceinline__ u64 ffma2(u64 a, u64 b, u64 c) {
    u64 d; asm("fma.rn.f32x2 %0, %1, %2, %3;" : "=l"(d) : "l"(a), "l"(b), "l"(c)); return d;
}
__device__ __forceinline__ void cp16(uint32_t s, const void* g) {
    asm volatile("cp.async.cg.shared.global [%0], [%1], 16;" :: "r"(s), "l"(g));
}

__device__ __forceinline__ float warp_sum(float v) {
    v += __shfl_xor_sync(FULLM, v, 16);
    v += __shfl_xor_sync(FULLM, v, 8);
    v += __shfl_xor_sync(FULLM, v, 4);
    v += __shfl_xor_sync(FULLM, v, 2);
    v += __shfl_xor_sync(FULLM, v, 1);
    return v;
}

__device__ __forceinline__ void mma_tf32(float& c0, float& c1, float& c2, float& c3,
                                         float a0, float a1, float b) {
    asm volatile(
        "mma.sync.aligned.m16n8k4.row.col.f32.tf32.tf32.f32 "
        "{%0,%1,%2,%3}, {%4,%5}, {%6}, {%0,%1,%2,%3};"
        : "+f"(c0), "+f"(c1), "+f"(c2), "+f"(c3)
        : "r"(__float_as_uint(a0)), "r"(__float_as_uint(a1)), "r"(__float_as_uint(b)));
}

// ============================================================================
// Kernel 1: assignment via tf32 MMA with A/B-phase tile streaming.
// Per tile (16 rows): jobs 0-3 = dot/argmax quarters (DRAM), jobs 4-7 =
// re-fetch quarters (L2) and accumulate normalized rows into per-warp smem acc.
// ============================================================================
extern __shared__ char dsm[];

__global__ void __launch_bounds__(A_TPB, 3)
k_assign(const float* __restrict__ src, const float* __restrict__ protos, int N)
{
    const int tid  = threadIdx.x;
    const int lane = tid & 31;
    const int warp = tid >> 5;
    const int g    = lane >> 2;   // 0..7
    const int t    = lane & 3;    // 0..3

    float* s_p    = (float*)(dsm + OFF_P);
    float* tile   = (float*)(dsm + OFF_TILE) + warp * 4 * SLOTF;
    float* s_accw = (float*)(dsm + OFF_ACC) + warp * (K * D);
    float* s_accb = (float*)(dsm + OFF_ACC);
    int*   s_icnt = (int*)(dsm + OFF_ICNT);

    // protos -> smem, layout [q][k][AP]
    for (int e = tid; e < 4 * K * AP; e += A_TPB) {
        int blk = e / AP, c = e - blk * AP;
        int q = blk >> 3, k = blk & 7;
        s_p[e] = (c < 64) ? protos[k * D + q * 64 + c] : 0.0f;
    }
    for (int e = tid; e < A_WPB * K * D; e += A_TPB) s_accb[e] = 0.0f;
    __syncthreads();

    const uint32_t tbase = (uint32_t)__cvta_generic_to_shared(tile);

    const int gw     = blockIdx.x * A_WPB + warp;
    const int ntiles = (N + 15) >> 4;
    const int own    = (gw < ntiles) ? ((ntiles - 1 - gw) / A_WARPS + 1) : 0;
    const int Jmax   = own * 8;   // 8 jobs per tile (4 A-quarters + 4 B-quarters)

    auto issue = [&](int j) {
        const int slot = j & 3;
        int jd = (j < Jmax) ? j : (Jmax - 1);
        const int m  = jd >> 3;
        const int q  = jd & 3;          // quarter index for both A (p 0-3) and B (p 4-7)
        const int tt = gw + m * A_WARPS;
        const int row0 = tt << 4;
#pragma unroll
        for (int i = 0; i < 8; i++) {
            int u = i * 32 + lane;
            int r = u >> 4, c4 = u & 15;
            int row = row0 + r; if (row >= N) row = N - 1;
            cp16(tbase + (uint32_t)(slot * SLOTB) + (uint32_t)(r * AP + c4 * 4) * 4,
                 src + (size_t)row * D + q * 64 + c4 * 4);
        }
        asm volatile("cp.async.commit_group;" ::: "memory");
    };

    int cnt = 0;
    float c0 = 0.f, c1 = 0.f, c2 = 0.f, c3 = 0.f, ssg = 0.f, ssh = 0.f;
    int   lb0p = 0, lb1p = 0;
    float inv0p = 0.f, inv1p = 0.f;

    if (Jmax > 0) { issue(0); issue(1); }

    for (int j = 0; j < Jmax; j++) {
        asm volatile("cp.async.wait_group 1;" ::: "memory");
        __syncwarp();
        issue(j + 2);   // slot (j+2)&3 != slot j&3 — safe with 4-slot ring

        const int p    = j & 7;
        const int q    = p & 3;
        const int slot = j & 3;

        if (p < 4) {
            // ---- A-phase: dots + norm ----
            const float* A0 = tile + slot * SLOTF + g * AP + t;
            const float* A1 = tile + slot * SLOTF + (g + 8) * AP + t;
            const float* Bp = s_p + (q * 8 + g) * AP + t;
#pragma unroll
            for (int s = 0; s < 16; s++) {
                float a0 = A0[s * 4];
                float a1 = A1[s * 4];
                float bb = Bp[s * 4];
                ssg = fmaf(a0, a0, ssg);
                ssh = fmaf(a1, a1, ssh);
                mma_tf32(c0, c1, c2, c3, a0, a1, bb);
            }
            if (p == 3) {
                // norms across quad
                ssg += __shfl_xor_sync(FULLM, ssg, 1);
                ssg += __shfl_xor_sync(FULLM, ssg, 2);
                ssh += __shfl_xor_sync(FULLM, ssh, 1);
                ssh += __shfl_xor_sync(FULLM, ssh, 2);
                inv0p = rsqrtf(fmaxf(ssg, 1e-24f));
                inv1p = rsqrtf(fmaxf(ssh, 1e-24f));
                // per-row argmax with first-max tiebreak (within quad)
                float lv0 = c0; int lb0 = 2 * t;
                if (c1 > lv0) { lv0 = c1; lb0 = 2 * t + 1; }
                float lv1 = c2; int lb1 = 2 * t;
                if (c3 > lv1) { lv1 = c3; lb1 = 2 * t + 1; }
#pragma unroll
                for (int s = 1; s <= 2; s <<= 1) {
                    float ov0 = __shfl_xor_sync(FULLM, lv0, s);
                    int   ok0 = __shfl_xor_sync(FULLM, lb0, s);
                    if (ov0 > lv0 || (ov0 == lv0 && ok0 < lb0)) { lv0 = ov0; lb0 = ok0; }
                    float ov1 = __shfl_xor_sync(FULLM, lv1, s);
                    int   ok1 = __shfl_xor_sync(FULLM, lb1, s);
                    if (ov1 > lv1 || (ov1 == lv1 && ok1 < lb1)) { lv1 = ov1; lb1 = ok1; }
                }
                lb0p = lb0; lb1p = lb1;
                c0 = c1 = c2 = c3 = 0.f;
                ssg = ssh = 0.f;
            }
        } else {
            // ---- B-phase: accumulate quarter q of this tile from smem ----
            const int tt   = gw + (j >> 3) * A_WARPS;
            const int row0 = tt << 4;
            const float* T = tile + slot * SLOTF;
#pragma unroll
            for (int r2 = 0; r2 < 16; r2++) {
                const int row = row0 + r2;
                if (row < N) {
                    const int   srcl = (r2 & 7) * 4;
                    const int   bk   = (r2 < 8) ? __shfl_sync(FULLM, lb0p, srcl)
                                                : __shfl_sync(FULLM, lb1p, srcl);
                    const float inv  = (r2 < 8) ? __shfl_sync(FULLM, inv0p, srcl)
                                                : __shfl_sync(FULLM, inv1p, srcl);
                    const u64 rv = *(const u64*)(T + r2 * AP + 2 * lane);
                    u64* ac = (u64*)(s_accw + bk * D + q * 64 + 2 * lane);
                    *ac = ffma2(rv, pk2(inv, inv), *ac);
                    if (p == 4) cnt += (bk == (lane & 7));
                }
            }
        }
    }

    // counts (scale-invariant inflation, normalized away downstream)
    cnt += __shfl_xor_sync(FULLM, cnt, 8);
    cnt += __shfl_xor_sync(FULLM, cnt, 16);
    if (lane < K) s_icnt[warp * K + lane] = cnt;
    __syncthreads();

    for (int e = tid; e < K * D; e += A_TPB) {
        g_part_sums[blockIdx.x * (K * D) + e] = s_accb[e] + s_accb[e + K * D];
    }
    if (tid < K) {
        g_part_counts[blockIdx.x * K + tid] = s_icnt[tid] + s_icnt[K + tid];
    }
}

// ============================================================================
// Kernel 2: reduce A_GRID partial blocks -> 8 mid blocks
// ============================================================================
#define RCHUNK 56   // ceil(444 / 8)
__global__ void k_reduce1()
{
    const int be = blockIdx.x & 7;
    const int bb = blockIdx.x >> 3;
    const int e  = be * 256 + threadIdx.x;
    float s = 0.0f;
    const int b0 = bb * RCHUNK;
    const int b1 = min(b0 + RCHUNK, A_GRID);
    for (int b = b0; b < b1; b++) s += g_part_sums[b * (K * D) + e];
    g_mid[bb * (K * D) + e] = s;
}

// ============================================================================
// Kernel 3: final reduce + prototype EMA update + renormalize (1 block)
// ============================================================================
__global__ void k_update(const float* __restrict__ protos)
{
    __shared__ float s_sums[K * D];
    __shared__ int   s_cnt[K];

    const int tid  = threadIdx.x;
    const int lane = tid & 31;
    const int warp = tid >> 5;

    for (int e = tid; e < K * D; e += 256) {
        float s = 0.0f;
#pragma unroll
        for (int m = 0; m < 8; m++) s += g_mid[m * (K * D) + e];
        s_sums[e] = s;
    }
    {
        int c = 0;
        for (int b = lane; b < A_GRID; b += 32) c += g_part_counts[b * K + warp];
        c = __reduce_add_sync(FULLM, c);
        if (lane == 0) s_cnt[warp] = c;
    }
    __syncthreads();

    const int k = warp;
    const float4* s4 = (const float4*)s_sums;
    float4 s1 = s4[k * 64 + lane];
    float4 s2 = s4[k * 64 + 32 + lane];

    const int   c = s_cnt[k];
    const float rr = 1.0f / fmaxf((float)c, 1.0f);
    float4 m1 = make_float4(s1.x*rr, s1.y*rr, s1.z*rr, s1.w*rr);
    float4 m2 = make_float4(s2.x*rr, s2.y*rr, s2.z*rr, s2.w*rr);

    float ss = m1.x*m1.x + m1.y*m1.y + m1.z*m1.z + m1.w*m1.w
             + m2.x*m2.x + m2.y*m2.y + m2.z*m2.z + m2.w*m2.w;
    ss = warp_sum(ss);
    const float inv = 1.0f / fmaxf(sqrtf(ss), 1e-12f);

    const float4* p4 = (const float4*)protos;
    const float4 p1 = p4[k * 64 + lane];
    const float4 p2 = p4[k * 64 + 32 + lane];

    float4 u1, u2;
    if (c > 0) {
        u1 = make_float4(0.9f*p1.x + 0.1f*m1.x*inv, 0.9f*p1.y + 0.1f*m1.y*inv,
                         0.9f*p1.z + 0.1f*m1.z*inv, 0.9f*p1.w + 0.1f*m1.w*inv);
        u2 = make_float4(0.9f*p2.x + 0.1f*m2.x*inv, 0.9f*p2.y + 0.1f*m2.y*inv,
                         0.9f*p2.z + 0.1f*m2.z*inv, 0.9f*p2.w + 0.1f*m2.w*inv);
    } else {
        u1 = p1; u2 = p2;
    }

    float ss2 = u1.x*u1.x + u1.y*u1.y + u1.z*u1.z + u1.w*u1.w
              + u2.x*u2.x + u2.y*u2.y + u2.z*u2.z + u2.w*u2.w;
    ss2 = warp_sum(ss2);
    const float inv2 = 1.0f / fmaxf(sqrtf(ss2), 1e-12f);

    float4* o4 = (float4*)g_protos_new;
    o4[k * 64 + lane]      = make_float4(u1.x*inv2, u1.y*inv2, u1.z*inv2, u1.w*inv2);
    o4[k * 64 + 32 + lane] = make_float4(u2.x*inv2, u2.y*inv2, u2.z*inv2, u2.w*inv2);
}

// ============================================================================
// Kernel 4 (R9 verbatim): target loss via tf32 MMA, 4-slot quarter ring
// ============================================================================
__global__ void __launch_bounds__(L_TPB, 5)
k_loss(const float* __restrict__ tgt, int N)
{
    __shared__ float s_p[K * PITCH];
    __shared__ float s_tile[2][16 * PITCH];
    __shared__ float s_l[2];

    const int tid  = threadIdx.x;
    const int lane = tid & 31;
    const int warp = tid >> 5;
    const int g    = lane >> 2;
    const int t    = lane & 3;

    for (int e = tid; e < K * PITCH; e += L_TPB) {
        int k = e / PITCH, c = e - k * PITCH;
        s_p[e] = (c < D) ? g_protos_new[k * D + c] : 0.0f;
    }
    __syncthreads();

    const int gw     = blockIdx.x * 2 + warp;
    const int ntiles = (N + 15) >> 4;
    const int own    = (gw < ntiles) ? ((ntiles - 1 - gw) / L_TOTW + 1) : 0;
    const int Jmax   = own * 4;

    float* tile = s_tile[warp];
    const uint32_t tbase = (uint32_t)__cvta_generic_to_shared(tile);

    auto issue = [&](int j) {
        const int slot = j & 3;
        int jd = (j < Jmax) ? j : (Jmax - 1);
        const int tt = gw + (jd >> 2) * L_TOTW;
        const int q  = jd & 3;
        const int row0 = tt << 4;
#pragma unroll
        for (int i = 0; i < 8; i++) {
            int u = i * 32 + lane;
            int r = u >> 4, c = u & 15;
            int row = row0 + r; if (row >= N) row = N - 1;
            cp16(tbase + (uint32_t)(r * PITCH + slot * 64 + c * 4) * 4,
                 tgt + (size_t)row * D + q * 64 + c * 4);
        }
        asm volatile("cp.async.commit_group;" ::: "memory");
    };

    float lsum = 0.0f;
    float c0 = 0.f, c1 = 0.f, c2 = 0.f, c3 = 0.f, ssg = 0.f, ssh = 0.f;

    if (Jmax > 0) { issue(0); issue(1); }

    for (int j = 0; j < Jmax; j++) {
        asm volatile("cp.async.wait_group 1;" ::: "memory");
        __syncwarp();
        issue(j + 2);

        const int q = j & 3;
        const float* A0 = tile + g * PITCH + q * 64 + t;
        const float* A1 = tile + (g + 8) * PITCH + q * 64 + t;
        const float* Bp = s_p + g * PITCH + q * 64 + t;

#pragma unroll
        for (int s = 0; s < 16; s++) {
            float a0 = A0[s * 4];
            float a1 = A1[s * 4];
            float bb = Bp[s * 4];
            ssg = fmaf(a0, a0, ssg);
            ssh = fmaf(a1, a1, ssh);
            mma_tf32(c0, c1, c2, c3, a0, a1, bb);
        }

        if (q == 3) {
            ssg += __shfl_xor_sync(FULLM, ssg, 1);
            ssg += __shfl_xor_sync(FULLM, ssg, 2);
            ssh += __shfl_xor_sync(FULLM, ssh, 1);
            ssh += __shfl_xor_sync(FULLM, ssh, 2);
            float m0 = fmaxf(c0, c1);
            float m1 = fmaxf(c2, c3);
            m0 = fmaxf(m0, __shfl_xor_sync(FULLM, m0, 1));
            m0 = fmaxf(m0, __shfl_xor_sync(FULLM, m0, 2));
            m1 = fmaxf(m1, __shfl_xor_sync(FULLM, m1, 1));
            m1 = fmaxf(m1, __shfl_xor_sync(FULLM, m1, 2));

            const int tt = gw + (j >> 2) * L_TOTW;
            const int row0 = tt << 4;
            if (t == 0) {
                if (row0 + g < N)     lsum += m0 * rsqrtf(fmaxf(ssg, 1e-24f));
                if (row0 + 8 + g < N) lsum += m1 * rsqrtf(fmaxf(ssh, 1e-24f));
            }
            c0 = c1 = c2 = c3 = 0.f;
            ssg = ssh = 0.f;
        }
    }

    lsum = warp_sum(lsum);
    if (lane == 0) s_l[warp] = lsum;
    __syncthreads();
    if (tid == 0) g_part_loss[blockIdx.x] = s_l[0] + s_l[1];
}

// ============================================================================
// Kernel 5: final mean:  out = 1 - (sum of max cos) / Nt
// ============================================================================
__global__ void k_final(float* __restrict__ out, int Nt)
{
    __shared__ float sw[16];
    const int tid  = threadIdx.x;
    const int lane = tid & 31;
    const int warp = tid >> 5;

    float v = 0.0f;
    for (int i = tid; i < L_CTAS; i += 512) v += g_part_loss[i];
    v = warp_sum(v);
    if (lane == 0) sw[warp] = v;
    __syncthreads();
    if (tid == 0) {
        float s = 0.0f;
#pragma unroll
        for (int w = 0; w < 16; w++) s += sw[w];
        out[0] = 1.0f - s / (float)Nt;
    }
}

// ============================================================================
extern "C" void kernel_launch(void* const* d_in, const int* in_sizes, int n_in,
                              void* d_out, int out_size)
{
    const float* src    = (const float*)d_in[0];
    const float* tgt    = (const float*)d_in[1];
    const float* protos = (const float*)d_in[2];
    float* out = (float*)d_out;

    const int Ns = in_sizes[0] / D;
    const int Nt = in_sizes[1] / D;

    cudaFuncSetAttribute(k_assign, cudaFuncAttributeMaxDynamicSharedMemorySize, A_SMEM);

    k_assign<<<A_GRID, A_TPB, A_SMEM>>>(src, protos, Ns);
    k_reduce1<<<64, 256>>>();
    k_update<<<1, 256>>>(protos);
    k_loss<<<L_CTAS, L_TPB>>>(tgt, Nt);
    k_final<<<1, 512>>>(out, Nt);
}

// round 13
// speedup vs baseline: 1.3101x; 1.3101x over previous
#include <cuda_runtime.h>
#include <math.h>
#include <stdint.h>

#define D       256
#define K       8
#define FULLM   0xffffffffu

typedef unsigned long long u64;

// ---- k_assign (whole-tile MMA) config ----
#define A_TPB    64
#define A_WPB    2
#define A_GRID   296                  // 2 CTAs/SM * 148
#define A_TOTW   (A_GRID * A_WPB)     // 592 warps
#define PITCHA   260                  // floats/row; 260 mod 32 = 4 -> conflict-free
#define BUFF     (16 * PITCHA)        // floats per tile buffer (16640 B)
// dynamic smem offsets (bytes)
#define OFF_P    0                    // protos [q][k][68] = 8704 B
#define OFF_TILE 8704                 // 2 warps * 2 bufs * 16640 = 66560 B
#define OFF_ACC  75264                // 2 warps * 8192 = 16384 B
#define OFF_ICNT 91648                // 16 ints
#define A_SMEM   91712

// ---- k_loss (MMA) config — R9 verbatim ----
#define L_TPB   64
#define L_CTAS  740                   // 5 * 148
#define L_TOTW  (L_CTAS * 2)
#define PITCH   260

// ---- device scratch ----
__device__ float g_part_sums[A_GRID * K * D];
__device__ int   g_part_counts[A_GRID * K];
__device__ float g_mid[8 * K * D];
__device__ float g_part_loss[L_CTAS];
__device__ float g_protos_new[K * D];

// ---------------- helpers ----------------
__device__ __forceinline__ u64 pk2(float lo, float hi) {
    u64 r; asm("mov.b64 %0, {%1, %2};" : "=l"(r) : "f"(lo), "f"(hi)); return r;
}
__device__ __forceinline__ u64 ffma2(u64 a, u64 b, u64 c) {
    u64 d; asm("fma.rn.f32x2 %0, %1, %2, %3;" : "=l"(d) : "l"(a), "l"(b), "l"(c)); return d;
}
__device__ __forceinline__ void cp16(uint32_t s, const void* g) {
    asm volatile("cp.async.cg.shared.global [%0], [%1], 16;" :: "r"(s), "l"(g));
}

__device__ __forceinline__ float warp_sum(float v) {
    v += __shfl_xor_sync(FULLM, v, 16);
    v += __shfl_xor_sync(FULLM, v, 8);
    v += __shfl_xor_sync(FULLM, v, 4);
    v += __shfl_xor_sync(FULLM, v, 2);
    v += __shfl_xor_sync(FULLM, v, 1);
    return v;
}

__device__ __forceinline__ void mma_tf32(float& c0, float& c1, float& c2, float& c3,
                                         float a0, float a1, float b) {
    asm volatile(
        "mma.sync.aligned.m16n8k4.row.col.f32.tf32.tf32.f32 "
        "{%0,%1,%2,%3}, {%4,%5}, {%6}, {%0,%1,%2,%3};"
        : "+f"(c0), "+f"(c1), "+f"(c2), "+f"(c3)
        : "r"(__float_as_uint(a0)), "r"(__float_as_uint(a1)), "r"(__float_as_uint(b)));
}

// ============================================================================
// Kernel 1: assignment via tf32 MMA with whole-tile double buffering.
// One warp = one 16-row tile at a time; accumulate from resident smem buffer.
// ============================================================================
extern __shared__ char dsm[];

__global__ void __launch_bounds__(A_TPB, 2)
k_assign(const float* __restrict__ src, const float* __restrict__ protos, int N)
{
    const int tid  = threadIdx.x;
    const int lane = tid & 31;
    const int warp = tid >> 5;
    const int g    = lane >> 2;   // 0..7
    const int t    = lane & 3;    // 0..3

    float* s_p    = (float*)(dsm + OFF_P);
    float* tile_w = (float*)(dsm + OFF_TILE) + warp * 2 * BUFF;
    float* s_accw = (float*)(dsm + OFF_ACC) + warp * (K * D);
    float* s_accb = (float*)(dsm + OFF_ACC);
    int*   s_icnt = (int*)(dsm + OFF_ICNT);

    // protos -> smem, layout [q][k][68]
    for (int e = tid; e < 4 * K * 68; e += A_TPB) {
        int blk = e / 68, c = e - blk * 68;
        int q = blk >> 3, k = blk & 7;
        s_p[e] = (c < 64) ? protos[k * D + q * 64 + c] : 0.0f;
    }
    for (int e = tid; e < A_WPB * K * D; e += A_TPB) s_accb[e] = 0.0f;
    __syncthreads();

    const uint32_t tbase = (uint32_t)__cvta_generic_to_shared(tile_w);

    const int gw     = blockIdx.x * A_WPB + warp;
    const int ntiles = (N + 15) >> 4;
    const int own    = (gw < ntiles) ? ((ntiles - 1 - gw) / A_TOTW + 1) : 0;

    auto issue = [&](int m) {
        int mm = (m < own) ? m : (own - 1);
        const int tt   = gw + mm * A_TOTW;
        const int row0 = tt << 4;
        const uint32_t sb = tbase + (uint32_t)((m & 1) * (BUFF * 4));
#pragma unroll
        for (int i = 0; i < 32; i++) {
            int u = i * 32 + lane;
            int r = u >> 6, c4 = u & 63;    // 64 chunks of 16B per 256-float row
            int row = row0 + r; if (row >= N) row = N - 1;
            cp16(sb + (uint32_t)(r * (PITCHA * 4) + c4 * 16),
                 src + (size_t)row * D + c4 * 4);
        }
        asm volatile("cp.async.commit_group;" ::: "memory");
    };

    int cnt = 0;

    if (own > 0) { issue(0); issue(1); }

    for (int m = 0; m < own; m++) {
        asm volatile("cp.async.wait_group 1;" ::: "memory");
        __syncwarp();

        float* buf = tile_w + (m & 1) * BUFF;
        float c0 = 0.f, c1 = 0.f, c2 = 0.f, c3 = 0.f, ssg = 0.f, ssh = 0.f;

#pragma unroll
        for (int q = 0; q < 4; q++) {
            const float* A0 = buf + g * PITCHA + q * 64 + t;
            const float* A1 = buf + (g + 8) * PITCHA + q * 64 + t;
            const float* Bp = s_p + (q * 8 + g) * 68 + t;
#pragma unroll
            for (int s = 0; s < 16; s++) {
                float a0 = A0[s * 4];
                float a1 = A1[s * 4];
                float bb = Bp[s * 4];
                ssg = fmaf(a0, a0, ssg);
                ssh = fmaf(a1, a1, ssh);
                mma_tf32(c0, c1, c2, c3, a0, a1, bb);
            }
        }

        // norms across quad (fp32 exact)
        ssg += __shfl_xor_sync(FULLM, ssg, 1);
        ssg += __shfl_xor_sync(FULLM, ssg, 2);
        ssh += __shfl_xor_sync(FULLM, ssh, 1);
        ssh += __shfl_xor_sync(FULLM, ssh, 2);
        const float inv0 = rsqrtf(fmaxf(ssg, 1e-24f));
        const float inv1 = rsqrtf(fmaxf(ssh, 1e-24f));

        // per-row argmax, first-max tiebreak (within quad)
        float lv0 = c0; int lb0 = 2 * t;
        if (c1 > lv0) { lv0 = c1; lb0 = 2 * t + 1; }
        float lv1 = c2; int lb1 = 2 * t;
        if (c3 > lv1) { lv1 = c3; lb1 = 2 * t + 1; }
#pragma unroll
        for (int s = 1; s <= 2; s <<= 1) {
            float ov0 = __shfl_xor_sync(FULLM, lv0, s);
            int   ok0 = __shfl_xor_sync(FULLM, lb0, s);
            if (ov0 > lv0 || (ov0 == lv0 && ok0 < lb0)) { lv0 = ov0; lb0 = ok0; }
            float ov1 = __shfl_xor_sync(FULLM, lv1, s);
            int   ok1 = __shfl_xor_sync(FULLM, lb1, s);
            if (ov1 > lv1 || (ov1 == lv1 && ok1 < lb1)) { lv1 = ov1; lb1 = ok1; }
        }

        // accumulate all 16 rows from the STILL-RESIDENT buffer
        const int tt   = gw + m * A_TOTW;
        const int row0 = tt << 4;
#pragma unroll
        for (int r2 = 0; r2 < 16; r2++) {
            const int row = row0 + r2;
            if (row < N) {
                const int   srcl = (r2 & 7) * 4;
                const int   bk   = (r2 < 8) ? __shfl_sync(FULLM, lb0, srcl)
                                            : __shfl_sync(FULLM, lb1, srcl);
                const float inv  = (r2 < 8) ? __shfl_sync(FULLM, inv0, srcl)
                                            : __shfl_sync(FULLM, inv1, srcl);
                cnt += (bk == (lane & 7));
                const u64 iv = pk2(inv, inv);
                const float* Tr = buf + r2 * PITCHA;
                const ulonglong2 x0 = *(const ulonglong2*)(Tr + 4 * lane);
                const ulonglong2 x1 = *(const ulonglong2*)(Tr + 128 + 4 * lane);
                ulonglong2* a0p = (ulonglong2*)(s_accw + bk * D + 4 * lane);
                ulonglong2* a1p = (ulonglong2*)(s_accw + bk * D + 128 + 4 * lane);
                ulonglong2 v0 = *a0p;
                v0.x = ffma2(x0.x, iv, v0.x);
                v0.y = ffma2(x0.y, iv, v0.y);
                *a0p = v0;
                ulonglong2 v1 = *a1p;
                v1.x = ffma2(x1.x, iv, v1.x);
                v1.y = ffma2(x1.y, iv, v1.y);
                *a1p = v1;
            }
        }
        __syncwarp();

        issue(m + 2);   // refill the buffer we just finished with
    }

    asm volatile("cp.async.wait_group 0;" ::: "memory");
    __syncwarp();

    // counts (4x inflated; cancels in normalize downstream)
    cnt += __shfl_xor_sync(FULLM, cnt, 8);
    cnt += __shfl_xor_sync(FULLM, cnt, 16);
    if (lane < K) s_icnt[warp * K + lane] = cnt;
    __syncthreads();

    for (int e = tid; e < K * D; e += A_TPB) {
        g_part_sums[blockIdx.x * (K * D) + e] = s_accb[e] + s_accb[e + K * D];
    }
    if (tid < K) {
        g_part_counts[blockIdx.x * K + tid] = s_icnt[tid] + s_icnt[K + tid];
    }
}

// ============================================================================
// Kernel 2: reduce A_GRID partial blocks -> 8 mid blocks
// ============================================================================
#define RCHUNK 37   // ceil(296 / 8)
__global__ void k_reduce1()
{
    const int be = blockIdx.x & 7;
    const int bb = blockIdx.x >> 3;
    const int e  = be * 256 + threadIdx.x;
    float s = 0.0f;
    const int b0 = bb * RCHUNK;
    const int b1 = min(b0 + RCHUNK, A_GRID);
    for (int b = b0; b < b1; b++) s += g_part_sums[b * (K * D) + e];
    g_mid[bb * (K * D) + e] = s;
}

// ============================================================================
// Kernel 3: final reduce + prototype EMA update + renormalize (1 block)
// ============================================================================
__global__ void k_update(const float* __restrict__ protos)
{
    __shared__ float s_sums[K * D];
    __shared__ int   s_cnt[K];

    const int tid  = threadIdx.x;
    const int lane = tid & 31;
    const int warp = tid >> 5;

    for (int e = tid; e < K * D; e += 256) {
        float s = 0.0f;
#pragma unroll
        for (int m = 0; m < 8; m++) s += g_mid[m * (K * D) + e];
        s_sums[e] = s;
    }
    {
        int c = 0;
        for (int b = lane; b < A_GRID; b += 32) c += g_part_counts[b * K + warp];
        c = __reduce_add_sync(FULLM, c);
        if (lane == 0) s_cnt[warp] = c;
    }
    __syncthreads();

    const int k = warp;
    const float4* s4 = (const float4*)s_sums;
    float4 s1 = s4[k * 64 + lane];
    float4 s2 = s4[k * 64 + 32 + lane];

    const int   c = s_cnt[k];
    const float rr = 1.0f / fmaxf((float)c, 1.0f);
    float4 m1 = make_float4(s1.x*rr, s1.y*rr, s1.z*rr, s1.w*rr);
    float4 m2 = make_float4(s2.x*rr, s2.y*rr, s2.z*rr, s2.w*rr);

    float ss = m1.x*m1.x + m1.y*m1.y + m1.z*m1.z + m1.w*m1.w
             + m2.x*m2.x + m2.y*m2.y + m2.z*m2.z + m2.w*m2.w;
    ss = warp_sum(ss);
    const float inv = 1.0f / fmaxf(sqrtf(ss), 1e-12f);

    const float4* p4 = (const float4*)protos;
    const float4 p1 = p4[k * 64 + lane];
    const float4 p2 = p4[k * 64 + 32 + lane];

    float4 u1, u2;
    if (c > 0) {
        u1 = make_float4(0.9f*p1.x + 0.1f*m1.x*inv, 0.9f*p1.y + 0.1f*m1.y*inv,
                         0.9f*p1.z + 0.1f*m1.z*inv, 0.9f*p1.w + 0.1f*m1.w*inv);
        u2 = make_float4(0.9f*p2.x + 0.1f*m2.x*inv, 0.9f*p2.y + 0.1f*m2.y*inv,
                         0.9f*p2.z + 0.1f*m2.z*inv, 0.9f*p2.w + 0.1f*m2.w*inv);
    } else {
        u1 = p1; u2 = p2;
    }

    float ss2 = u1.x*u1.x + u1.y*u1.y + u1.z*u1.z + u1.w*u1.w
              + u2.x*u2.x + u2.y*u2.y + u2.z*u2.z + u2.w*u2.w;
    ss2 = warp_sum(ss2);
    const float inv2 = 1.0f / fmaxf(sqrtf(ss2), 1e-12f);

    float4* o4 = (float4*)g_protos_new;
    o4[k * 64 + lane]      = make_float4(u1.x*inv2, u1.y*inv2, u1.z*inv2, u1.w*inv2);
    o4[k * 64 + 32 + lane] = make_float4(u2.x*inv2, u2.y*inv2, u2.z*inv2, u2.w*inv2);
}

// ============================================================================
// Kernel 4 (R9 verbatim): target loss via tf32 MMA, 4-slot quarter ring
// ============================================================================
__global__ void __launch_bounds__(L_TPB, 5)
k_loss(const float* __restrict__ tgt, int N)
{
    __shared__ float s_p[K * PITCH];
    __shared__ float s_tile[2][16 * PITCH];
    __shared__ float s_l[2];

    const int tid  = threadIdx.x;
    const int lane = tid & 31;
    const int warp = tid >> 5;
    const int g    = lane >> 2;
    const int t    = lane & 3;

    for (int e = tid; e < K * PITCH; e += L_TPB) {
        int k = e / PITCH, c = e - k * PITCH;
        s_p[e] = (c < D) ? g_protos_new[k * D + c] : 0.0f;
    }
    __syncthreads();

    const int gw     = blockIdx.x * 2 + warp;
    const int ntiles = (N + 15) >> 4;
    const int own    = (gw < ntiles) ? ((ntiles - 1 - gw) / L_TOTW + 1) : 0;
    const int Jmax   = own * 4;

    float* tile = s_tile[warp];
    const uint32_t tbase = (uint32_t)__cvta_generic_to_shared(tile);

    auto issue = [&](int j) {
        const int slot = j & 3;
        int jd = (j < Jmax) ? j : (Jmax - 1);
        const int tt = gw + (jd >> 2) * L_TOTW;
        const int q  = jd & 3;
        const int row0 = tt << 4;
#pragma unroll
        for (int i = 0; i < 8; i++) {
            int u = i * 32 + lane;
            int r = u >> 4, c = u & 15;
            int row = row0 + r; if (row >= N) row = N - 1;
            cp16(tbase + (uint32_t)(r * PITCH + slot * 64 + c * 4) * 4,
                 tgt + (size_t)row * D + q * 64 + c * 4);
        }
        asm volatile("cp.async.commit_group;" ::: "memory");
    };

    float lsum = 0.0f;
    float c0 = 0.f, c1 = 0.f, c2 = 0.f, c3 = 0.f, ssg = 0.f, ssh = 0.f;

    if (Jmax > 0) { issue(0); issue(1); }

    for (int j = 0; j < Jmax; j++) {
        asm volatile("cp.async.wait_group 1;" ::: "memory");
        __syncwarp();
        issue(j + 2);

        const int q = j & 3;
        const float* A0 = tile + g * PITCH + q * 64 + t;
        const float* A1 = tile + (g + 8) * PITCH + q * 64 + t;
        const float* Bp = s_p + g * PITCH + q * 64 + t;

#pragma unroll
        for (int s = 0; s < 16; s++) {
            float a0 = A0[s * 4];
            float a1 = A1[s * 4];
            float bb = Bp[s * 4];
            ssg = fmaf(a0, a0, ssg);
            ssh = fmaf(a1, a1, ssh);
            mma_tf32(c0, c1, c2, c3, a0, a1, bb);
        }

        if (q == 3) {
            ssg += __shfl_xor_sync(FULLM, ssg, 1);
            ssg += __shfl_xor_sync(FULLM, ssg, 2);
            ssh += __shfl_xor_sync(FULLM, ssh, 1);
            ssh += __shfl_xor_sync(FULLM, ssh, 2);
            float m0 = fmaxf(c0, c1);
            float m1 = fmaxf(c2, c3);
            m0 = fmaxf(m0, __shfl_xor_sync(FULLM, m0, 1));
            m0 = fmaxf(m0, __shfl_xor_sync(FULLM, m0, 2));
            m1 = fmaxf(m1, __shfl_xor_sync(FULLM, m1, 1));
            m1 = fmaxf(m1, __shfl_xor_sync(FULLM, m1, 2));

            const int tt = gw + (j >> 2) * L_TOTW;
            const int row0 = tt << 4;
            if (t == 0) {
                if (row0 + g < N)     lsum += m0 * rsqrtf(fmaxf(ssg, 1e-24f));
                if (row0 + 8 + g < N) lsum += m1 * rsqrtf(fmaxf(ssh, 1e-24f));
            }
            c0 = c1 = c2 = c3 = 0.f;
            ssg = ssh = 0.f;
        }
    }

    lsum = warp_sum(lsum);
    if (lane == 0) s_l[warp] = lsum;
    __syncthreads();
    if (tid == 0) g_part_loss[blockIdx.x] = s_l[0] + s_l[1];
}

// ============================================================================
// Kernel 5: final mean:  out = 1 - (sum of max cos) / Nt
// ============================================================================
__global__ void k_final(float* __restrict__ out, int Nt)
{
    __shared__ float sw[16];
    const int tid  = threadIdx.x;
    const int lane = tid & 31;
    const int warp = tid >> 5;

    float v = 0.0f;
    for (int i = tid; i < L_CTAS; i += 512) v += g_part_loss[i];
    v = warp_sum(v);
    if (lane == 0) sw[warp] = v;
    __syncthreads();
    if (tid == 0) {
        float s = 0.0f;
#pragma unroll
        for (int w = 0; w < 16; w++) s += sw[w];
        out[0] = 1.0f - s / (float)Nt;
    }
}

// ============================================================================
extern "C" void kernel_launch(void* const* d_in, const int* in_sizes, int n_in,
                              void* d_out, int out_size)
{
    const float* src    = (const float*)d_in[0];
    const float* tgt    = (const float*)d_in[1];
    const float* protos = (const float*)d_in[2];
    float* out = (float*)d_out;

    const int Ns = in_sizes[0] / D;
    const int Nt = in_sizes[1] / D;

    cudaFuncSetAttribute(k_assign, cudaFuncAttributeMaxDynamicSharedMemorySize, A_SMEM);

    k_assign<<<A_GRID, A_TPB, A_SMEM>>>(src, protos, Ns);
    k_reduce1<<<64, 256>>>();
    k_update<<<1, 256>>>(protos);
    k_loss<<<L_CTAS, L_TPB>>>(tgt, Nt);
    k_final<<<1, 512>>>(out, Nt);
}

// round 14
// speedup vs baseline: 1.4801x; 1.1298x over previous
#include <cuda_runtime.h>
#include <math.h>
#include <stdint.h>

#define D       256
#define K       8
#define FULLM   0xffffffffu

typedef unsigned long long u64;

// ---- k_assign (full-MMA) config ----
#define A_TPB    96
#define A_WPB    3
#define A_GRID   296                  // 2 CTAs/SM * 148
#define A_TOTW   (A_GRID * A_WPB)     // 888 warps
#define AP       68                   // quarter pitch (floats)
#define SLOTF    (16 * AP)            // 1088 floats per slot
#define SLOTB    (SLOTF * 4)          // 4352 B
// dynamic smem offsets (bytes)
#define OFF_P    0                    // protos [q][k][68] = 8704 B
#define OFF_TILE 8704                 // 3 warps * 8 slots * 4352 = 104448 B
#define OFF_ICNT 113152               // 24 ints
#define A_SMEM   113248

// ---- k_loss (MMA) config — R9 verbatim ----
#define L_TPB   64
#define L_CTAS  740                   // 5 * 148
#define L_TOTW  (L_CTAS * 2)
#define PITCH   260

// ---- device scratch ----
__device__ float g_part_sums[A_TOTW * K * D];   // per-WARP partials (888)
__device__ int   g_part_counts[A_GRID * K];
__device__ float g_mid[8 * K * D];
__device__ float g_part_loss[L_CTAS];
__device__ float g_protos_new[K * D];

// ---------------- helpers ----------------
__device__ __forceinline__ void cp16(uint32_t s, const void* g) {
    asm volatile("cp.async.cg.shared.global [%0], [%1], 16;" :: "r"(s), "l"(g));
}

__device__ __forceinline__ float warp_sum(float v) {
    v += __shfl_xor_sync(FULLM, v, 16);
    v += __shfl_xor_sync(FULLM, v, 8);
    v += __shfl_xor_sync(FULLM, v, 4);
    v += __shfl_xor_sync(FULLM, v, 2);
    v += __shfl_xor_sync(FULLM, v, 1);
    return v;
}

__device__ __forceinline__ void mma_tf32(float& c0, float& c1, float& c2, float& c3,
                                         float a0, float a1, float b) {
    asm volatile(
        "mma.sync.aligned.m16n8k4.row.col.f32.tf32.tf32.f32 "
        "{%0,%1,%2,%3}, {%4,%5}, {%6}, {%0,%1,%2,%3};"
        : "+f"(c0), "+f"(c1), "+f"(c2), "+f"(c3)
        : "r"(__float_as_uint(a0)), "r"(__float_as_uint(a1)), "r"(__float_as_uint(b)));
}

__device__ __forceinline__ void mma_k8(float* C,
                                       float a0, float a1, float a2, float a3,
                                       float b0, float b1) {
    asm volatile(
        "mma.sync.aligned.m16n8k8.row.col.f32.tf32.tf32.f32 "
        "{%0,%1,%2,%3}, {%4,%5,%6,%7}, {%8,%9}, {%0,%1,%2,%3};"
        : "+f"(C[0]), "+f"(C[1]), "+f"(C[2]), "+f"(C[3])
        : "r"(__float_as_uint(a0)), "r"(__float_as_uint(a1)),
          "r"(__float_as_uint(a2)), "r"(__float_as_uint(a3)),
          "r"(__float_as_uint(b0)), "r"(__float_as_uint(b1)));
}

// ============================================================================
// Kernel 1: assignment fully on the tensor pipe.
// Dots: m16n8k4 (X·Pᵀ). Accumulate: m16n8k8 with one-hot weight B-fragment,
// C = 64 persistent regs = per-warp S[K][D] partial. 8-slot quarter ring keeps
// the whole 16-row tile resident until its argmax is known.
// ============================================================================
extern __shared__ char dsm[];

__global__ void __launch_bounds__(A_TPB, 2)
k_assign(const float* __restrict__ src, const float* __restrict__ protos, int N)
{
    const int tid  = threadIdx.x;
    const int lane = tid & 31;
    const int warp = tid >> 5;
    const int g    = lane >> 2;   // 0..7
    const int t    = lane & 3;    // 0..3

    float* s_p    = (float*)(dsm + OFF_P);
    float* tile_w = (float*)(dsm + OFF_TILE) + warp * 8 * SLOTF;
    int*   s_icnt = (int*)(dsm + OFF_ICNT);

    // protos -> smem, layout [q][k][68]
    for (int e = tid; e < 4 * K * AP; e += A_TPB) {
        int blk = e / AP, c = e - blk * AP;
        int q = blk >> 3, k = blk & 7;
        s_p[e] = (c < 64) ? protos[k * D + q * 64 + c] : 0.0f;
    }
    __syncthreads();

    const uint32_t tbase = (uint32_t)__cvta_generic_to_shared(tile_w);

    const int gw     = blockIdx.x * A_WPB + warp;
    const int ntiles = (N + 15) >> 4;
    const int own    = (gw < ntiles) ? ((ntiles - 1 - gw) / A_TOTW + 1) : 0;
    const int Jmax   = own * 4;

    auto issue = [&](int j) {
        const int slot = j & 7;
        int jd = (j < Jmax) ? j : (Jmax - 1);
        const int tt = gw + (jd >> 2) * A_TOTW;
        const int q  = jd & 3;
        const int row0 = tt << 4;
#pragma unroll
        for (int i = 0; i < 8; i++) {
            int u = i * 32 + lane;
            int r = u >> 4, c4 = u & 15;
            int row = row0 + r; if (row >= N) row = N - 1;
            cp16(tbase + (uint32_t)(slot * SLOTB) + (uint32_t)(r * AP + c4 * 4) * 4,
                 src + (size_t)row * D + q * 64 + c4 * 4);
        }
        asm volatile("cp.async.commit_group;" ::: "memory");
    };

    // persistent S accumulators: S[ci][0..3] = S[d=16ci+g / +8][k=2t / 2t+1]
    float S[16][4];
#pragma unroll
    for (int ci = 0; ci < 16; ci++)
#pragma unroll
        for (int e = 0; e < 4; e++) S[ci][e] = 0.f;

    float ce0=0.f,ce1=0.f,ce2=0.f,ce3=0.f;    // dot accumulators (even s)
    float co0=0.f,co1=0.f,co2=0.f,co3=0.f;    // dot accumulators (odd s)
    float ssg = 0.f, ssh = 0.f;
    int cnt = 0;

    if (Jmax > 0) {
#pragma unroll
        for (int p = 0; p < 5; p++) issue(p);
    }

    for (int j = 0; j < Jmax; j++) {
        asm volatile("cp.async.wait_group 4;" ::: "memory");
        __syncwarp();

        const int q    = j & 3;
        const int slot = j & 7;
        const float* A0 = tile_w + slot * SLOTF + g * AP + t;
        const float* A1 = tile_w + slot * SLOTF + (g + 8) * AP + t;
        const float* Bp = s_p + (q * 8 + g) * AP + t;

#pragma unroll
        for (int s = 0; s < 16; s++) {
            float a0 = A0[s * 4];
            float a1 = A1[s * 4];
            float bb = Bp[s * 4];
            ssg = fmaf(a0, a0, ssg);
            ssh = fmaf(a1, a1, ssh);
            if (s & 1) mma_tf32(co0, co1, co2, co3, a0, a1, bb);
            else       mma_tf32(ce0, ce1, ce2, ce3, a0, a1, bb);
        }

        if (q == 3) {
            // ---- norms (fp32 exact) ----
            ssg += __shfl_xor_sync(FULLM, ssg, 1);
            ssg += __shfl_xor_sync(FULLM, ssg, 2);
            ssh += __shfl_xor_sync(FULLM, ssh, 1);
            ssh += __shfl_xor_sync(FULLM, ssh, 2);
            const float inv0 = rsqrtf(fmaxf(ssg, 1e-24f));
            const float inv1 = rsqrtf(fmaxf(ssh, 1e-24f));

            // ---- combine dot sets, argmax (first-max tiebreak) ----
            float v0 = ce0 + co0, v1 = ce1 + co1, v2 = ce2 + co2, v3 = ce3 + co3;
            float lv0 = v0; int lb0 = 2 * t;
            if (v1 > lv0) { lv0 = v1; lb0 = 2 * t + 1; }
            float lv1 = v2; int lb1 = 2 * t;
            if (v3 > lv1) { lv1 = v3; lb1 = 2 * t + 1; }
#pragma unroll
            for (int s = 1; s <= 2; s <<= 1) {
                float ov0 = __shfl_xor_sync(FULLM, lv0, s);
                int   ok0 = __shfl_xor_sync(FULLM, lb0, s);
                if (ov0 > lv0 || (ov0 == lv0 && ok0 < lb0)) { lv0 = ov0; lb0 = ok0; }
                float ov1 = __shfl_xor_sync(FULLM, lv1, s);
                int   ok1 = __shfl_xor_sync(FULLM, lb1, s);
                if (ov1 > lv1 || (ov1 == lv1 && ok1 < lb1)) { lv1 = ov1; lb1 = ok1; }
            }

            const int tt   = gw + (j >> 2) * A_TOTW;
            const int row0 = tt << 4;

            // ---- build one-hot B fragments (col = g, rows via t) ----
            // h=0 covers rows 0..7 (b0: row t, b1: row t+4); h=1 rows 8..15.
            int   bk_a = __shfl_sync(FULLM, lb0, 4 * t);
            float iv_a = __shfl_sync(FULLM, inv0, 4 * t);
            int   bk_b = __shfl_sync(FULLM, lb0, 4 * (t + 4));
            float iv_b = __shfl_sync(FULLM, inv0, 4 * (t + 4));
            int   bk_c = __shfl_sync(FULLM, lb1, 4 * t);
            float iv_c = __shfl_sync(FULLM, inv1, 4 * t);
            int   bk_d = __shfl_sync(FULLM, lb1, 4 * (t + 4));
            float iv_d = __shfl_sync(FULLM, inv1, 4 * (t + 4));
            float w00 = (bk_a == g && row0 + t      < N) ? iv_a : 0.f;
            float w10 = (bk_b == g && row0 + t + 4  < N) ? iv_b : 0.f;
            float w01 = (bk_c == g && row0 + 8 + t  < N) ? iv_c : 0.f;
            float w11 = (bk_d == g && row0 + 12 + t < N) ? iv_d : 0.f;

            // ---- accumulate S += Wᵀ X via 32 independent m16n8k8 MMAs ----
            const int sbase = (j - 3) & 7;   // slot of quarter 0 of this tile (0 or 4)
#pragma unroll
            for (int ci = 0; ci < 16; ci++) {
                const int   qq = ci >> 2;
                const int   dl = (ci & 3) * 16;
                const float* Tq = tile_w + (sbase + qq) * SLOTF;
                // h = 0: rows 0..7
                float a0 = Tq[t * AP + dl + g];
                float a1 = Tq[t * AP + dl + g + 8];
                float a2 = Tq[(t + 4) * AP + dl + g];
                float a3 = Tq[(t + 4) * AP + dl + g + 8];
                mma_k8(S[ci], a0, a1, a2, a3, w00, w10);
                // h = 1: rows 8..15
                float b0 = Tq[(8 + t) * AP + dl + g];
                float b1 = Tq[(8 + t) * AP + dl + g + 8];
                float b2 = Tq[(12 + t) * AP + dl + g];
                float b3 = Tq[(12 + t) * AP + dl + g + 8];
                mma_k8(S[ci], b0, b1, b2, b3, w01, w11);
            }

            // ---- counts (4x inflated; cancels in normalize) ----
#pragma unroll
            for (int r2 = 0; r2 < 16; r2++) {
                if (row0 + r2 < N) {
                    const int srcl = (r2 & 7) * 4;
                    const int bk = (r2 < 8) ? __shfl_sync(FULLM, lb0, srcl)
                                            : __shfl_sync(FULLM, lb1, srcl);
                    cnt += (bk == (lane & 7));
                }
            }

            ce0=ce1=ce2=ce3=0.f; co0=co1=co2=co3=0.f;
            ssg = ssh = 0.f;
        }

        issue(j + 5);   // at q==3 this is quarter 1 of tile m+2 -> other slot half
    }

    asm volatile("cp.async.wait_group 0;" ::: "memory");
    __syncwarp();

    // counts
    cnt += __shfl_xor_sync(FULLM, cnt, 8);
    cnt += __shfl_xor_sync(FULLM, cnt, 16);
    if (lane < K) s_icnt[warp * K + lane] = cnt;

    // write per-warp S partial
    {
        float* base = g_part_sums + (size_t)gw * (K * D);
#pragma unroll
        for (int ci = 0; ci < 16; ci++) {
            const int d = ci * 16 + g;
            base[(2 * t) * D + d]         = S[ci][0];
            base[(2 * t + 1) * D + d]     = S[ci][1];
            base[(2 * t) * D + d + 8]     = S[ci][2];
            base[(2 * t + 1) * D + d + 8] = S[ci][3];
        }
    }
    __syncthreads();
    if (tid < K) {
        g_part_counts[blockIdx.x * K + tid] =
            s_icnt[tid] + s_icnt[K + tid] + s_icnt[2 * K + tid];
    }
}

// ============================================================================
// Kernel 2: reduce A_TOTW (888) warp partials -> 8 mid blocks
// ============================================================================
#define RCHUNKA 111   // 888 / 8
__global__ void k_reduce1()
{
    const int be = blockIdx.x & 7;
    const int bb = blockIdx.x >> 3;
    const int e  = be * 256 + threadIdx.x;
    float s = 0.0f;
    const int b0 = bb * RCHUNKA;
    const int b1 = min(b0 + RCHUNKA, A_TOTW);
    for (int b = b0; b < b1; b++) s += g_part_sums[(size_t)b * (K * D) + e];
    g_mid[bb * (K * D) + e] = s;
}

// ============================================================================
// Kernel 3: final reduce + prototype EMA update + renormalize (1 block)
// ============================================================================
__global__ void k_update(const float* __restrict__ protos)
{
    __shared__ float s_sums[K * D];
    __shared__ int   s_cnt[K];

    const int tid  = threadIdx.x;
    const int lane = tid & 31;
    const int warp = tid >> 5;

    for (int e = tid; e < K * D; e += 256) {
        float s = 0.0f;
#pragma unroll
        for (int m = 0; m < 8; m++) s += g_mid[m * (K * D) + e];
        s_sums[e] = s;
    }
    {
        int c = 0;
        for (int b = lane; b < A_GRID; b += 32) c += g_part_counts[b * K + warp];
        c = __reduce_add_sync(FULLM, c);
        if (lane == 0) s_cnt[warp] = c;
    }
    __syncthreads();

    const int k = warp;
    const float4* s4 = (const float4*)s_sums;
    float4 s1 = s4[k * 64 + lane];
    float4 s2 = s4[k * 64 + 32 + lane];

    const int   c = s_cnt[k];
    const float rr = 1.0f / fmaxf((float)c, 1.0f);
    float4 m1 = make_float4(s1.x*rr, s1.y*rr, s1.z*rr, s1.w*rr);
    float4 m2 = make_float4(s2.x*rr, s2.y*rr, s2.z*rr, s2.w*rr);

    float ss = m1.x*m1.x + m1.y*m1.y + m1.z*m1.z + m1.w*m1.w
             + m2.x*m2.x + m2.y*m2.y + m2.z*m2.z + m2.w*m2.w;
    ss = warp_sum(ss);
    const float inv = 1.0f / fmaxf(sqrtf(ss), 1e-12f);

    const float4* p4 = (const float4*)protos;
    const float4 p1 = p4[k * 64 + lane];
    const float4 p2 = p4[k * 64 + 32 + lane];

    float4 u1, u2;
    if (c > 0) {
        u1 = make_float4(0.9f*p1.x + 0.1f*m1.x*inv, 0.9f*p1.y + 0.1f*m1.y*inv,
                         0.9f*p1.z + 0.1f*m1.z*inv, 0.9f*p1.w + 0.1f*m1.w*inv);
        u2 = make_float4(0.9f*p2.x + 0.1f*m2.x*inv, 0.9f*p2.y + 0.1f*m2.y*inv,
                         0.9f*p2.z + 0.1f*m2.z*inv, 0.9f*p2.w + 0.1f*m2.w*inv);
    } else {
        u1 = p1; u2 = p2;
    }

    float ss2 = u1.x*u1.x + u1.y*u1.y + u1.z*u1.z + u1.w*u1.w
              + u2.x*u2.x + u2.y*u2.y + u2.z*u2.z + u2.w*u2.w;
    ss2 = warp_sum(ss2);
    const float inv2 = 1.0f / fmaxf(sqrtf(ss2), 1e-12f);

    float4* o4 = (float4*)g_protos_new;
    o4[k * 64 + lane]      = make_float4(u1.x*inv2, u1.y*inv2, u1.z*inv2, u1.w*inv2);
    o4[k * 64 + 32 + lane] = make_float4(u2.x*inv2, u2.y*inv2, u2.z*inv2, u2.w*inv2);
}

// ============================================================================
// Kernel 4 (R9 verbatim): target loss via tf32 MMA, 4-slot quarter ring
// ============================================================================
__global__ void __launch_bounds__(L_TPB, 5)
k_loss(const float* __restrict__ tgt, int N)
{
    __shared__ float s_p[K * PITCH];
    __shared__ float s_tile[2][16 * PITCH];
    __shared__ float s_l[2];

    const int tid  = threadIdx.x;
    const int lane = tid & 31;
    const int warp = tid >> 5;
    const int g    = lane >> 2;
    const int t    = lane & 3;

    for (int e = tid; e < K * PITCH; e += L_TPB) {
        int k = e / PITCH, c = e - k * PITCH;
        s_p[e] = (c < D) ? g_protos_new[k * D + c] : 0.0f;
    }
    __syncthreads();

    const int gw     = blockIdx.x * 2 + warp;
    const int ntiles = (N + 15) >> 4;
    const int own    = (gw < ntiles) ? ((ntiles - 1 - gw) / L_TOTW + 1) : 0;
    const int Jmax   = own * 4;

    float* tile = s_tile[warp];
    const uint32_t tbase = (uint32_t)__cvta_generic_to_shared(tile);

    auto issue = [&](int j) {
        const int slot = j & 3;
        int jd = (j < Jmax) ? j : (Jmax - 1);
        const int tt = gw + (jd >> 2) * L_TOTW;
        const int q  = jd & 3;
        const int row0 = tt << 4;
#pragma unroll
        for (int i = 0; i < 8; i++) {
            int u = i * 32 + lane;
            int r = u >> 4, c = u & 15;
            int row = row0 + r; if (row >= N) row = N - 1;
            cp16(tbase + (uint32_t)(r * PITCH + slot * 64 + c * 4) * 4,
                 tgt + (size_t)row * D + q * 64 + c * 4);
        }
        asm volatile("cp.async.commit_group;" ::: "memory");
    };

    float lsum = 0.0f;
    float c0 = 0.f, c1 = 0.f, c2 = 0.f, c3 = 0.f, ssg = 0.f, ssh = 0.f;

    if (Jmax > 0) { issue(0); issue(1); }

    for (int j = 0; j < Jmax; j++) {
        asm volatile("cp.async.wait_group 1;" ::: "memory");
        __syncwarp();
        issue(j + 2);

        const int q = j & 3;
        const float* A0 = tile + g * PITCH + q * 64 + t;
        const float* A1 = tile + (g + 8) * PITCH + q * 64 + t;
        const float* Bp = s_p + g * PITCH + q * 64 + t;

#pragma unroll
        for (int s = 0; s < 16; s++) {
            float a0 = A0[s * 4];
            float a1 = A1[s * 4];
            float bb = Bp[s * 4];
            ssg = fmaf(a0, a0, ssg);
            ssh = fmaf(a1, a1, ssh);
            mma_tf32(c0, c1, c2, c3, a0, a1, bb);
        }

        if (q == 3) {
            ssg += __shfl_xor_sync(FULLM, ssg, 1);
            ssg += __shfl_xor_sync(FULLM, ssg, 2);
            ssh += __shfl_xor_sync(FULLM, ssh, 1);
            ssh += __shfl_xor_sync(FULLM, ssh, 2);
            float m0 = fmaxf(c0, c1);
            float m1 = fmaxf(c2, c3);
            m0 = fmaxf(m0, __shfl_xor_sync(FULLM, m0, 1));
            m0 = fmaxf(m0, __shfl_xor_sync(FULLM, m0, 2));
            m1 = fmaxf(m1, __shfl_xor_sync(FULLM, m1, 1));
            m1 = fmaxf(m1, __shfl_xor_sync(FULLM, m1, 2));

            const int tt = gw + (j >> 2) * L_TOTW;
            const int row0 = tt << 4;
            if (t == 0) {
                if (row0 + g < N)     lsum += m0 * rsqrtf(fmaxf(ssg, 1e-24f));
                if (row0 + 8 + g < N) lsum += m1 * rsqrtf(fmaxf(ssh, 1e-24f));
            }
            c0 = c1 = c2 = c3 = 0.f;
            ssg = ssh = 0.f;
        }
    }

    lsum = warp_sum(lsum);
    if (lane == 0) s_l[warp] = lsum;
    __syncthreads();
    if (tid == 0) g_part_loss[blockIdx.x] = s_l[0] + s_l[1];
}

// ============================================================================
// Kernel 5: final mean:  out = 1 - (sum of max cos) / Nt
// ============================================================================
__global__ void k_final(float* __restrict__ out, int Nt)
{
    __shared__ float sw[16];
    const int tid  = threadIdx.x;
    const int lane = tid & 31;
    const int warp = tid >> 5;

    float v = 0.0f;
    for (int i = tid; i < L_CTAS; i += 512) v += g_part_loss[i];
    v = warp_sum(v);
    if (lane == 0) sw[warp] = v;
    __syncthreads();
    if (tid == 0) {
        float s = 0.0f;
#pragma unroll
        for (int w = 0; w < 16; w++) s += sw[w];
        out[0] = 1.0f - s / (float)Nt;
    }
}

// ============================================================================
extern "C" void kernel_launch(void* const* d_in, const int* in_sizes, int n_in,
                              void* d_out, int out_size)
{
    const float* src    = (const float*)d_in[0];
    const float* tgt    = (const float*)d_in[1];
    const float* protos = (const float*)d_in[2];
    float* out = (float*)d_out;

    const int Ns = in_sizes[0] / D;
    const int Nt = in_sizes[1] / D;

    cudaFuncSetAttribute(k_assign, cudaFuncAttributeMaxDynamicSharedMemorySize, A_SMEM);

    k_assign<<<A_GRID, A_TPB, A_SMEM>>>(src, protos, Ns);
    k_reduce1<<<64, 256>>>();
    k_update<<<1, 256>>>(protos);
    k_loss<<<L_CTAS, L_TPB>>>(tgt, Nt);
    k_final<<<1, 512>>>(out, Nt);
}